// round 16
// baseline (speedup 1.0000x reference)
#include <cuda_runtime.h>
#include <math.h>
#include <stdint.h>

// Problem constants
#define BB     8
#define NSEQ   512
#define DIMD   512
#define DEPTH  6
#define HEADS  8
#define DH     64
#define INNER  512          // HEADS*DH
#define ROWS   4096         // BB*NSEQ
#define EPSL   1e-5f
#define ASCALE 0.125f       // DH^-0.5

// ---------------------------------------------------------------------------
// Scratch (~40 MB). w/qkv fp32 buffer lives in d_out.
// g_zp: 4 bf16 planes {rH,rL,iH,iL} of the activation operand (z1 / ao / z2).
// g_ws: per-layer pre-split weight planes for qkv/out/ff.
// ---------------------------------------------------------------------------
__device__ float g_x_r[ROWS * DIMD];
__device__ float g_x_i[ROWS * DIMD];
#define PL (ROWS * DIMD)
__device__ uint16_t g_zp[4 * PL];          // 16.8 MB
#define WELEM (512 * 512)
__device__ uint16_t g_ws[3 * 4 * WELEM];   // 6.3 MB

// ---------------------------------------------------------------------------
// Common mma/split helpers (verified R5-R15)
// ---------------------------------------------------------------------------
__device__ __forceinline__ void mma16(float* c, const uint32_t* a, const uint32_t* b) {
    asm volatile(
        "mma.sync.aligned.m16n8k16.row.col.f32.bf16.bf16.f32 "
        "{%0,%1,%2,%3}, {%4,%5,%6,%7}, {%8,%9}, {%0,%1,%2,%3};\n"
        : "+f"(c[0]), "+f"(c[1]), "+f"(c[2]), "+f"(c[3])
        : "r"(a[0]), "r"(a[1]), "r"(a[2]), "r"(a[3]), "r"(b[0]), "r"(b[1]));
}
__device__ __forceinline__ uint32_t pkbf(float lo_val, float hi_val) {
    uint32_t r;
    asm("cvt.rn.bf16x2.f32 %0, %1, %2;" : "=r"(r) : "f"(hi_val), "f"(lo_val));
    return r;
}
__device__ __forceinline__ uint32_t hi2(float a, float b) {
    uint32_t r;
    asm("prmt.b32 %0, %1, %2, 0x7632;" : "=r"(r)
        : "r"(__float_as_uint(a)), "r"(__float_as_uint(b)));
    return r;
}
__device__ __forceinline__ float lof(float a) {
    return a - __uint_as_float(__float_as_uint(a) & 0xffff0000u);
}
__device__ __forceinline__ void st_split(uint16_t* hiP, uint16_t* loP, int e, float4 v) {
    *(uint2*)&hiP[e] = make_uint2(hi2(v.x, v.y), hi2(v.z, v.w));
    *(uint2*)&loP[e] = make_uint2(pkbf(lof(v.x), lof(v.y)), pkbf(lof(v.z), lof(v.w)));
}
__device__ __forceinline__ void ldsm4(uint32_t* d, const uint16_t* p) {
    uint32_t a = (uint32_t)__cvta_generic_to_shared(p);
    asm volatile("ldmatrix.sync.aligned.m8n8.x4.shared.b16 {%0,%1,%2,%3}, [%4];"
        : "=r"(d[0]), "=r"(d[1]), "=r"(d[2]), "=r"(d[3]) : "r"(a));
}
__device__ __forceinline__ void ldsm4t(uint32_t* d, const uint16_t* p) {
    uint32_t a = (uint32_t)__cvta_generic_to_shared(p);
    asm volatile("ldmatrix.sync.aligned.m8n8.x4.trans.shared.b16 {%0,%1,%2,%3}, [%4];"
        : "=r"(d[0]), "=r"(d[1]), "=r"(d[2]), "=r"(d[3]) : "r"(a));
}
__device__ __forceinline__ void cpa16(const uint16_t* smem_dst, const uint16_t* gsrc) {
    uint32_t d = (uint32_t)__cvta_generic_to_shared(smem_dst);
    asm volatile("cp.async.cg.shared.global [%0], [%1], 16;" :: "r"(d), "l"(gsrc));
}
__device__ __forceinline__ float bf_lo(uint32_t p) {
    return __uint_as_float(p << 16);
}
__device__ __forceinline__ float bf_hi(uint32_t p) {
    return __uint_as_float(p & 0xffff0000u);
}

// ---------------------------------------------------------------------------
// Weight splitter (verified R14): 3 matrices -> 4 bf16 planes each.
// ---------------------------------------------------------------------------
__global__ __launch_bounds__(256) void split3_kernel(
    const float* __restrict__ qwr, const float* __restrict__ qwi,
    const float* __restrict__ owr, const float* __restrict__ owi,
    const float* __restrict__ fwr, const float* __restrict__ fwi)
{
    int seg = blockIdx.x >> 8;
    int idx = (blockIdx.x & 255) * 256 + threadIdx.x;
    const float* wr = (seg == 0) ? qwr : (seg == 1) ? owr : fwr;
    const float* wi = (seg == 0) ? qwi : (seg == 1) ? owi : fwi;
    uint16_t* base = g_ws + (size_t)seg * 4 * WELEM;

    float4 vr = ((const float4*)wr)[idx];
    float4 vi = ((const float4*)wi)[idx];
    int e = idx * 4;
    *(uint2*)&base[e]             = make_uint2(hi2(vr.x, vr.y), hi2(vr.z, vr.w));
    *(uint2*)&base[WELEM + e]     = make_uint2(pkbf(lof(vr.x), lof(vr.y)),
                                               pkbf(lof(vr.z), lof(vr.w)));
    *(uint2*)&base[2 * WELEM + e] = make_uint2(hi2(vi.x, vi.y), hi2(vi.z, vi.w));
    *(uint2*)&base[3 * WELEM + e] = make_uint2(pkbf(lof(vi.x), lof(vi.y)),
                                               pkbf(lof(vi.z), lof(vi.w)));
}

// ---------------------------------------------------------------------------
// Block reduction helper (256 threads)
// ---------------------------------------------------------------------------
__device__ __forceinline__ float block_reduce(float v, float* sh, bool ismax) {
    #pragma unroll
    for (int o = 16; o; o >>= 1) {
        float u = __shfl_xor_sync(0xffffffffu, v, o);
        v = ismax ? fmaxf(v, u) : (v + u);
    }
    int w = threadIdx.x >> 5;
    if ((threadIdx.x & 31) == 0) sh[w] = v;
    __syncthreads();
    if (threadIdx.x < 32) {
        float u = (threadIdx.x < 8) ? sh[threadIdx.x] : (ismax ? -INFINITY : 0.0f);
        #pragma unroll
        for (int o = 4; o; o >>= 1) {
            float t2 = __shfl_xor_sync(0xffffffffu, u, o);
            u = ismax ? fmaxf(u, t2) : (u + t2);
        }
        if (threadIdx.x == 0) sh[0] = u;
    }
    __syncthreads();
    float r = sh[0];
    __syncthreads();
    return r;
}

// ---------------------------------------------------------------------------
// Complex LayerNorm writing bf16 hi/lo planes. One block per row of 512.
// Thread t handles cols 2t, 2t+1 (u32 plane stores).
// ---------------------------------------------------------------------------
__global__ __launch_bounds__(256) void cln_kernel(
    const float* __restrict__ xr, const float* __restrict__ xi,
    const float* __restrict__ gr, const float* __restrict__ br,
    const float* __restrict__ gi, const float* __restrict__ bi,
    uint16_t* __restrict__ zp)
{
    __shared__ float sh[8];
    int row = blockIdx.x;
    int t = threadIdx.x;
    const float* pr = xr + (size_t)row * DIMD;
    const float* pi = xi + (size_t)row * DIMD;

    float2 vr = *(const float2*)&pr[2 * t];
    float2 vi2 = *(const float2*)&pi[2 * t];

    float sr  = block_reduce(vr.x + vr.y, sh, false);
    float ssr = block_reduce(vr.x * vr.x + vr.y * vr.y, sh, false);
    float si  = block_reduce(vi2.x + vi2.y, sh, false);
    float ssi = block_reduce(vi2.x * vi2.x + vi2.y * vi2.y, sh, false);

    float mr = sr * (1.0f / DIMD);
    float varr = fmaxf(ssr * (1.0f / DIMD) - mr * mr, 0.0f);
    float rsr = rsqrtf(varr + EPSL);
    float mi = si * (1.0f / DIMD);
    float vari = fmaxf(ssi * (1.0f / DIMD) - mi * mi, 0.0f);
    float rsi = rsqrtf(vari + EPSL);

    float zr0 = (vr.x - mr) * rsr * gr[2 * t]     + br[2 * t];
    float zr1 = (vr.y - mr) * rsr * gr[2 * t + 1] + br[2 * t + 1];
    float zi0 = (vi2.x - mi) * rsi * gi[2 * t]     + bi[2 * t];
    float zi1 = (vi2.y - mi) * rsi * gi[2 * t + 1] + bi[2 * t + 1];

    size_t e = (size_t)row * DIMD + 2 * t;
    *(uint32_t*)&zp[e]          = hi2(zr0, zr1);
    *(uint32_t*)&zp[PL + e]     = pkbf(lof(zr0), lof(zr1));
    *(uint32_t*)&zp[2 * PL + e] = hi2(zi0, zi1);
    *(uint32_t*)&zp[3 * PL + e] = pkbf(lof(zi0), lof(zi1));
}

// ---------------------------------------------------------------------------
// bf16x3 complex NT GEMM — cp.async deep pipeline (fetch distance 3),
// pre-split bf16 operands (A = activation planes, B = weight planes).
// CTA 128x128, BK=16, 256 threads, warp tile 32x64, 4-stage smem ring.
// Epilogues: 0 plain / 1 residual+bias / 2 ISTA+CReLU (z2 = hi+lo reconstruct).
// ---------------------------------------------------------------------------
#define PADK 24
#define APLN (128 * PADK)
#define STG  (8 * APLN)              // one stage (8 planes)
#define CG_SMEM (4 * STG * 2)        // 4-stage ring = 196608 bytes

#define LD32(P, r, k) (*(const uint32_t*)&(P)[(r) * PADK + (k)])

template <int EPI>
__global__ __launch_bounds__(256) void cgemm_ca(
    const uint16_t* __restrict__ Apl,   // 4 planes [4096][512], stride PL
    const uint16_t* __restrict__ Bpl,   // 4 planes [512][512], stride WELEM
    float* __restrict__ Cr, float* __restrict__ Ci, int ldc, int K,
    const float* __restrict__ biasr, const float* __restrict__ biasi,
    const float* __restrict__ stepp, const float* __restrict__ lamp, int l)
{
    extern __shared__ uint16_t smem16[];

    int tid = threadIdx.x;
    int lane = tid & 31, w = tid >> 5;
    int wm = (w & 3) * 32, wn = (w >> 2) * 64;
    int gid = lane >> 2, tig = lane & 3;
    int row0 = blockIdx.y * 128, col0 = blockIdx.x * 128;

    float cr[2][8][4] = {}, ci[2][8][4] = {};

    // cp.async one stage: 8 planes x 128 rows x 16 u16; 8 x 16B per thread.
    #define ISSUE(s)                                                           \
        {                                                                      \
            int k0 = (s) * 16;                                                 \
            uint16_t* dst = smem16 + ((s) & 3) * STG;                          \
            _Pragma("unroll")                                                  \
            for (int i = 0; i < 8; i++) {                                      \
                int linear = tid + i * 256;                                    \
                int p = linear >> 8;                                           \
                int rem = linear & 255;                                        \
                int r = rem >> 1, half = rem & 1;                              \
                const uint16_t* src = (p < 4)                                  \
                    ? Apl + (size_t)p * PL + (size_t)(row0 + r) * 512 + k0 + half * 8 \
                    : Bpl + (size_t)(p - 4) * WELEM + (size_t)(col0 + r) * 512 + k0 + half * 8; \
                cpa16(dst + p * APLN + r * PADK + half * 8, src);              \
            }                                                                  \
        }

    #define MMAST(BASE)                                                        \
        {                                                                      \
            const uint16_t* ARH = (BASE);                                      \
            const uint16_t* ARL = (BASE) + APLN;                               \
            const uint16_t* AIH = (BASE) + 2 * APLN;                           \
            const uint16_t* AIL = (BASE) + 3 * APLN;                           \
            const uint16_t* BRH = (BASE) + 4 * APLN;                           \
            const uint16_t* BRL = (BASE) + 5 * APLN;                           \
            const uint16_t* BIH = (BASE) + 6 * APLN;                           \
            const uint16_t* BIL = (BASE) + 7 * APLN;                           \
            int kk = tig * 2;                                                  \
            uint32_t aRH[2][4], aRL[2][4], aIH[2][4], aIL[2][4];               \
            _Pragma("unroll")                                                  \
            for (int mt = 0; mt < 2; mt++) {                                   \
                int r = wm + mt * 16 + gid;                                    \
                aRH[mt][0] = LD32(ARH, r, kk);     aRH[mt][1] = LD32(ARH, r + 8, kk); \
                aRH[mt][2] = LD32(ARH, r, kk + 8); aRH[mt][3] = LD32(ARH, r + 8, kk + 8); \
                aRL[mt][0] = LD32(ARL, r, kk);     aRL[mt][1] = LD32(ARL, r + 8, kk); \
                aRL[mt][2] = LD32(ARL, r, kk + 8); aRL[mt][3] = LD32(ARL, r + 8, kk + 8); \
                aIH[mt][0] = LD32(AIH, r, kk);     aIH[mt][1] = LD32(AIH, r + 8, kk); \
                aIH[mt][2] = LD32(AIH, r, kk + 8); aIH[mt][3] = LD32(AIH, r + 8, kk + 8); \
                aIL[mt][0] = LD32(AIL, r, kk);     aIL[mt][1] = LD32(AIL, r + 8, kk); \
                aIL[mt][2] = LD32(AIL, r, kk + 8); aIL[mt][3] = LD32(AIL, r + 8, kk + 8); \
            }                                                                  \
            _Pragma("unroll")                                                  \
            for (int nt = 0; nt < 8; nt++) {                                   \
                int c = wn + nt * 8 + gid;                                     \
                uint32_t bRH[2] = { LD32(BRH, c, kk), LD32(BRH, c, kk + 8) };  \
                uint32_t bRL[2] = { LD32(BRL, c, kk), LD32(BRL, c, kk + 8) };  \
                uint32_t bIH[2] = { LD32(BIH, c, kk), LD32(BIH, c, kk + 8) };  \
                uint32_t bIL[2] = { LD32(BIL, c, kk), LD32(BIL, c, kk + 8) };  \
                uint32_t nIH[2] = { bIH[0] ^ 0x80008000u, bIH[1] ^ 0x80008000u }; \
                uint32_t nIL[2] = { bIL[0] ^ 0x80008000u, bIL[1] ^ 0x80008000u }; \
                _Pragma("unroll")                                              \
                for (int mt = 0; mt < 2; mt++) {                               \
                    mma16(cr[mt][nt], aRH[mt], bRH);                           \
                    mma16(cr[mt][nt], aRH[mt], bRL);                           \
                    mma16(cr[mt][nt], aRL[mt], bRH);                           \
                    mma16(cr[mt][nt], aIH[mt], nIH);                           \
                    mma16(cr[mt][nt], aIH[mt], nIL);                           \
                    mma16(cr[mt][nt], aIL[mt], nIH);                           \
                    mma16(ci[mt][nt], aRH[mt], bIH);                           \
                    mma16(ci[mt][nt], aRH[mt], bIL);                           \
                    mma16(ci[mt][nt], aRL[mt], bIH);                           \
                    mma16(ci[mt][nt], aIH[mt], bRH);                           \
                    mma16(ci[mt][nt], aIH[mt], bRL);                           \
                    mma16(ci[mt][nt], aIL[mt], bRH);                           \
                }                                                              \
            }                                                                  \
        }

    int nstage = K >> 4;
    // prologue: stages 0..2 in flight
    ISSUE(0); asm volatile("cp.async.commit_group;");
    ISSUE(1); asm volatile("cp.async.commit_group;");
    ISSUE(2); asm volatile("cp.async.commit_group;");

    for (int s = 0; s < nstage; s++) {
        asm volatile("cp.async.wait_group 2;");
        __syncthreads();
        if (s + 3 < nstage) ISSUE(s + 3);
        asm volatile("cp.async.commit_group;");
        MMAST(smem16 + (s & 3) * STG);
    }
    #undef ISSUE
    #undef MMAST

    float ps = 0.0f, pl2 = 0.0f;
    if (EPI == 2) {
        ps = log1pf(expf(stepp[l]));
        pl2 = log1pf(expf(lamp[l]));
    }

    #pragma unroll
    for (int mt = 0; mt < 2; mt++)
        #pragma unroll
        for (int nt = 0; nt < 8; nt++) {
            int m0 = row0 + wm + mt * 16 + gid;
            int n0 = col0 + wn + nt * 8 + tig * 2;
            #pragma unroll
            for (int half = 0; half < 2; half++) {
                int m = m0 + half * 8;
                float vr0 = cr[mt][nt][half * 2 + 0];
                float vr1 = cr[mt][nt][half * 2 + 1];
                float vi0 = ci[mt][nt][half * 2 + 0];
                float vi1 = ci[mt][nt][half * 2 + 1];
                size_t idx = (size_t)m * ldc + n0;
                if (EPI == 0) {
                    Cr[idx]     = vr0;  Cr[idx + 1] = vr1;
                    Ci[idx]     = vi0;  Ci[idx + 1] = vi1;
                } else if (EPI == 1) {
                    Cr[idx]     += vr0 + biasr[n0];
                    Cr[idx + 1] += vr1 + biasr[n0 + 1];
                    Ci[idx]     += vi0 + biasi[n0];
                    Ci[idx + 1] += vi1 + biasi[n0 + 1];
                } else {
                    // reconstruct z2 = hi + lo from planes
                    size_t za = (size_t)m * 512 + n0;
                    uint32_t hr = *(const uint32_t*)&Apl[za];
                    uint32_t lr = *(const uint32_t*)&Apl[PL + za];
                    uint32_t hi = *(const uint32_t*)&Apl[2 * PL + za];
                    uint32_t li = *(const uint32_t*)&Apl[3 * PL + za];
                    float zr0 = bf_lo(hr) + bf_lo(lr);
                    float zr1 = bf_hi(hr) + bf_hi(lr);
                    float zi0 = bf_lo(hi) + bf_lo(li);
                    float zi1 = bf_hi(hi) + bf_hi(li);
                    Cr[idx]     = fmaxf(zr0 + ps * vr0 - ps * pl2, 0.0f);
                    Cr[idx + 1] = fmaxf(zr1 + ps * vr1 - ps * pl2, 0.0f);
                    Ci[idx]     = fmaxf(zi0 + ps * vi0, 0.0f);
                    Ci[idx + 1] = fmaxf(zi1 + ps * vi1, 0.0f);
                }
            }
        }
}

// ---------------------------------------------------------------------------
// Tensor-core flash attention (bf16x3) — R9/R11 body; epilogue writes ao
// directly as bf16 hi/lo planes (consumed by the out-proj GEMM).
// ---------------------------------------------------------------------------
#define FSTR 72
#define QPL (64 * FSTR)
#define KPL (64 * FSTR)
#define FLASH_SMEM ((4 * QPL + 4 * KPL) * 2)   // 73728 bytes

__global__ __launch_bounds__(128, 2) void flash_mma_kernel(
    const float* __restrict__ Wr, const float* __restrict__ Wi,
    uint16_t* __restrict__ opl)
{
    extern __shared__ uint16_t fsm[];
    uint16_t* QRH = fsm;
    uint16_t* QRL = QRH + QPL;
    uint16_t* QIH = QRL + QPL;
    uint16_t* QIL = QIH + QPL;
    uint16_t* KRH = QIL + QPL;
    uint16_t* KRL = KRH + KPL;
    uint16_t* KIH = KRL + KPL;
    uint16_t* KIL = KIH + KPL;

    int tid = threadIdx.x;
    int lane = tid & 31, w = tid >> 5;
    int q0 = blockIdx.x * 64;
    int bh = blockIdx.y;
    int b = bh >> 3, h = bh & 7;

    const float* baseR = Wr + (size_t)b * NSEQ * INNER + h * DH;
    const float* baseI = Wi + (size_t)b * NSEQ * INNER + h * DH;

    #pragma unroll
    for (int i = 0; i < 8; i++) {
        int linear = tid + i * 128;
        int row = linear >> 4, c4 = linear & 15;
        float4 v = *(const float4*)&baseR[(size_t)(q0 + row) * INNER + c4 * 4];
        st_split(QRH, QRL, row * FSTR + c4 * 4, v);
        v = *(const float4*)&baseI[(size_t)(q0 + row) * INNER + c4 * 4];
        st_split(QIH, QIL, row * FSTR + c4 * 4, v);
    }

    int a_off = (16 * w + (lane & 7) + ((lane >> 3) & 1) * 8) * FSTR
              + ((lane >> 4) & 1) * 8;
    int bd_off = ((lane & 7) + ((lane >> 4) & 1) * 8) * FSTR
               + ((lane >> 3) & 1) * 8;
    int bv_off = ((lane & 7) + ((lane >> 3) & 1) * 8) * FSTR
               + ((lane >> 4) & 1) * 8;

    float o_r[8][4] = {}, o_i[8][4] = {};
    float mrow[2] = { -1e30f, -1e30f };
    float lrow[2] = { 0.0f, 0.0f };

    for (int kt = 0; kt < 8; kt++) {
        __syncthreads();
        #pragma unroll
        for (int i = 0; i < 8; i++) {
            int linear = tid + i * 128;
            int key = linear >> 4, c4 = linear & 15;
            int e = key * FSTR + c4 * 4;
            float4 v = *(const float4*)&baseR[(size_t)(kt * 64 + key) * INNER + c4 * 4];
            st_split(KRH, KRL, e, v);
            v = *(const float4*)&baseI[(size_t)(kt * 64 + key) * INNER + c4 * 4];
            st_split(KIH, KIL, e, v);
        }
        __syncthreads();

        // ---- dots ----
        float dr[8][4] = {}, di[8][4] = {};
        #pragma unroll 1
        for (int ks = 0; ks < 4; ks++) {
            int ao2 = a_off + ks * 16;
            uint32_t aRH[4], aRL[4], aIH[4], aIL[4];
            ldsm4(aRH, QRH + ao2); ldsm4(aRL, QRL + ao2);
            ldsm4(aIH, QIH + ao2); ldsm4(aIL, QIL + ao2);
            #pragma unroll
            for (int nfp = 0; nfp < 4; nfp++) {
                int bo = bd_off + nfp * 16 * FSTR + ks * 16;
                uint32_t BRH[4], BRL[4], BIH[4], BIL[4];
                ldsm4(BRH, KRH + bo); ldsm4(BRL, KRL + bo);
                ldsm4(BIH, KIH + bo); ldsm4(BIL, KIL + bo);
                #pragma unroll
                for (int half = 0; half < 2; half++) {
                    int nf = 2 * nfp + half;
                    uint32_t bRH[2] = { BRH[2*half], BRH[2*half+1] };
                    uint32_t bRL[2] = { BRL[2*half], BRL[2*half+1] };
                    uint32_t bIH[2] = { BIH[2*half], BIH[2*half+1] };
                    uint32_t bIL[2] = { BIL[2*half], BIL[2*half+1] };
                    uint32_t nIH[2] = { bIH[0] ^ 0x80008000u, bIH[1] ^ 0x80008000u };
                    uint32_t nIL[2] = { bIL[0] ^ 0x80008000u, bIL[1] ^ 0x80008000u };
                    mma16(dr[nf], aRH, bRH); mma16(dr[nf], aRH, bRL); mma16(dr[nf], aRL, bRH);
                    mma16(dr[nf], aIH, bIH); mma16(dr[nf], aIH, bIL); mma16(dr[nf], aIL, bIH);
                    mma16(di[nf], aIH, bRH); mma16(di[nf], aIH, bRL); mma16(di[nf], aIL, bRH);
                    mma16(di[nf], aRH, nIH); mma16(di[nf], aRH, nIL); mma16(di[nf], aRL, nIH);
                }
            }
        }

        // ---- online softmax ----
        float m2max[2] = { -1.0f, -1.0f };
        #pragma unroll
        for (int nf = 0; nf < 8; nf++)
            #pragma unroll
            for (int e = 0; e < 4; e++) {
                float m2 = dr[nf][e] * dr[nf][e] + di[nf][e] * di[nf][e];
                m2max[e >> 1] = fmaxf(m2max[e >> 1], m2);
            }
        float mnew[2];
        #pragma unroll
        for (int half = 0; half < 2; half++) {
            float v = m2max[half];
            v = fmaxf(v, __shfl_xor_sync(0xffffffffu, v, 1));
            v = fmaxf(v, __shfl_xor_sync(0xffffffffu, v, 2));
            mnew[half] = fmaxf(mrow[half], ASCALE * sqrtf(fmaxf(v, 0.0f)));
        }
        float sc0 = __expf(mrow[0] - mnew[0]);
        float sc1 = __expf(mrow[1] - mnew[1]);
        lrow[0] *= sc0; lrow[1] *= sc1;
        mrow[0] = mnew[0]; mrow[1] = mnew[1];
        #pragma unroll
        for (int nf = 0; nf < 8; nf++) {
            o_r[nf][0] *= sc0; o_r[nf][1] *= sc0;
            o_r[nf][2] *= sc1; o_r[nf][3] *= sc1;
            o_i[nf][0] *= sc0; o_i[nf][1] *= sc0;
            o_i[nf][2] *= sc1; o_i[nf][3] *= sc1;
        }
        float rsum[2] = { 0.0f, 0.0f };
        #pragma unroll
        for (int nf = 0; nf < 8; nf++)
            #pragma unroll
            for (int e = 0; e < 4; e++) {
                float m2 = dr[nf][e] * dr[nf][e] + di[nf][e] * di[nf][e];
                if (m2 > 0.0f) {
                    float rs = rsqrtf(m2);
                    float s = m2 * rs;
                    float p = __expf(ASCALE * s - mrow[e >> 1]);
                    rsum[e >> 1] += p;
                    float f = p * rs;
                    dr[nf][e] *= f;
                    di[nf][e] *= f;
                } else {
                    float p = __expf(-mrow[e >> 1]);
                    rsum[e >> 1] += p;
                    dr[nf][e] = p;
                    di[nf][e] = 0.0f;
                }
            }
        #pragma unroll
        for (int half = 0; half < 2; half++) {
            float v = rsum[half];
            v += __shfl_xor_sync(0xffffffffu, v, 1);
            v += __shfl_xor_sync(0xffffffffu, v, 2);
            lrow[half] += v;
        }

        // ---- AV ----
        #pragma unroll
        for (int t = 0; t < 4; t++) {
            uint32_t PrH[4] = { hi2(dr[2*t][0], dr[2*t][1]),   hi2(dr[2*t][2], dr[2*t][3]),
                                hi2(dr[2*t+1][0], dr[2*t+1][1]), hi2(dr[2*t+1][2], dr[2*t+1][3]) };
            uint32_t PrL[4] = { pkbf(lof(dr[2*t][0]), lof(dr[2*t][1])),
                                pkbf(lof(dr[2*t][2]), lof(dr[2*t][3])),
                                pkbf(lof(dr[2*t+1][0]), lof(dr[2*t+1][1])),
                                pkbf(lof(dr[2*t+1][2]), lof(dr[2*t+1][3])) };
            uint32_t PiH[4] = { hi2(di[2*t][0], di[2*t][1]),   hi2(di[2*t][2], di[2*t][3]),
                                hi2(di[2*t+1][0], di[2*t+1][1]), hi2(di[2*t+1][2], di[2*t+1][3]) };
            uint32_t PiL[4] = { pkbf(lof(di[2*t][0]), lof(di[2*t][1])),
                                pkbf(lof(di[2*t][2]), lof(di[2*t][3])),
                                pkbf(lof(di[2*t+1][0]), lof(di[2*t+1][1])),
                                pkbf(lof(di[2*t+1][2]), lof(di[2*t+1][3])) };
            #pragma unroll
            for (int nfp = 0; nfp < 4; nfp++) {
                int bo = bv_off + t * 16 * FSTR + nfp * 16;
                uint32_t BRH[4], BRL[4], BIH[4], BIL[4];
                ldsm4t(BRH, KRH + bo); ldsm4t(BRL, KRL + bo);
                ldsm4t(BIH, KIH + bo); ldsm4t(BIL, KIL + bo);
                #pragma unroll
                for (int half = 0; half < 2; half++) {
                    int nf = 2 * nfp + half;
                    uint32_t bRH[2] = { BRH[2*half], BRH[2*half+1] };
                    uint32_t bRL[2] = { BRL[2*half], BRL[2*half+1] };
                    uint32_t bIH[2] = { BIH[2*half], BIH[2*half+1] };
                    uint32_t bIL[2] = { BIL[2*half], BIL[2*half+1] };
                    uint32_t nIH[2] = { bIH[0] ^ 0x80008000u, bIH[1] ^ 0x80008000u };
                    uint32_t nIL[2] = { bIL[0] ^ 0x80008000u, bIL[1] ^ 0x80008000u };
                    mma16(o_r[nf], PrH, bRH); mma16(o_r[nf], PrH, bRL); mma16(o_r[nf], PrL, bRH);
                    mma16(o_r[nf], PiH, nIH); mma16(o_r[nf], PiH, nIL); mma16(o_r[nf], PiL, nIH);
                    mma16(o_i[nf], PrH, bIH); mma16(o_i[nf], PrH, bIL); mma16(o_i[nf], PrL, bIH);
                    mma16(o_i[nf], PiH, bRH); mma16(o_i[nf], PiH, bRL); mma16(o_i[nf], PiL, bRH);
                }
            }
        }
    }

    // ---- normalize + write ao as bf16 hi/lo planes ----
    int gid = lane >> 2, tig = lane & 3;
    float inv0 = 1.0f / lrow[0];
    float inv1 = 1.0f / lrow[1];
    size_t row0g = (size_t)(b * NSEQ + q0 + 16 * w + gid);
    #pragma unroll
    for (int nf = 0; nf < 8; nf++) {
        int col = h * DH + nf * 8 + tig * 2;
        size_t e0 = row0g * INNER + col;
        size_t e1 = (row0g + 8) * INNER + col;
        float a0 = o_r[nf][0] * inv0, a1 = o_r[nf][1] * inv0;
        float b0 = o_r[nf][2] * inv1, b1 = o_r[nf][3] * inv1;
        float c0 = o_i[nf][0] * inv0, c1 = o_i[nf][1] * inv0;
        float d0 = o_i[nf][2] * inv1, d1 = o_i[nf][3] * inv1;
        *(uint32_t*)&opl[e0]          = hi2(a0, a1);
        *(uint32_t*)&opl[PL + e0]     = pkbf(lof(a0), lof(a1));
        *(uint32_t*)&opl[2 * PL + e0] = hi2(c0, c1);
        *(uint32_t*)&opl[3 * PL + e0] = pkbf(lof(c0), lof(c1));
        *(uint32_t*)&opl[e1]          = hi2(b0, b1);
        *(uint32_t*)&opl[PL + e1]     = pkbf(lof(b0), lof(b1));
        *(uint32_t*)&opl[2 * PL + e1] = hi2(d0, d1);
        *(uint32_t*)&opl[3 * PL + e1] = pkbf(lof(d0), lof(d1));
    }
}

__global__ __launch_bounds__(256) void init_kernel(
    const float* __restrict__ xr, const float* __restrict__ xi)
{
    int i = blockIdx.x * 256 + threadIdx.x;
    g_x_r[i] = xr[i];
    g_x_i[i] = xi[i];
}

__global__ __launch_bounds__(256) void output_kernel(float* __restrict__ out)
{
    int i = blockIdx.x * 256 + threadIdx.x;
    out[i] = g_x_r[i];
    out[i + ROWS * DIMD] = g_x_i[i];
}

// ---------------------------------------------------------------------------
// Launch
// ---------------------------------------------------------------------------
extern "C" void kernel_launch(void* const* d_in, const int* in_sizes, int n_in,
                              void* d_out, int out_size)
{
    const float* x_r   = (const float*)d_in[0];
    const float* x_i   = (const float*)d_in[1];
    const float* ln1gr = (const float*)d_in[2];
    const float* ln1gi = (const float*)d_in[3];
    const float* ln2gr = (const float*)d_in[4];
    const float* ln2gi = (const float*)d_in[5];
    const float* ln1br = (const float*)d_in[6];
    const float* ln1bi = (const float*)d_in[7];
    const float* ln2br = (const float*)d_in[8];
    const float* ln2bi = (const float*)d_in[9];
    const float* qkvwr = (const float*)d_in[10];
    const float* qkvwi = (const float*)d_in[11];
    const float* outwr = (const float*)d_in[12];
    const float* outwi = (const float*)d_in[13];
    const float* outbr = (const float*)d_in[14];
    const float* outbi = (const float*)d_in[15];
    const float* ffwr  = (const float*)d_in[16];
    const float* ffwi  = (const float*)d_in[17];
    const float* stepv = (const float*)d_in[18];
    const float* lambv = (const float*)d_in[19];

    const int EW = ROWS * DIMD;
    const dim3 gemm_grid(DIMD / 128, ROWS / 128);   // (4, 32)

    float* wr = (float*)d_out;
    float* wi = wr + (size_t)ROWS * INNER;

    float *xr, *xi;
    uint16_t *zp, *ws;
    cudaGetSymbolAddress((void**)&xr, g_x_r);
    cudaGetSymbolAddress((void**)&xi, g_x_i);
    cudaGetSymbolAddress((void**)&zp, g_zp);
    cudaGetSymbolAddress((void**)&ws, g_ws);

    cudaFuncSetAttribute(flash_mma_kernel,
                         cudaFuncAttributeMaxDynamicSharedMemorySize, FLASH_SMEM);
    cudaFuncSetAttribute(cgemm_ca<0>,
                         cudaFuncAttributeMaxDynamicSharedMemorySize, CG_SMEM);
    cudaFuncSetAttribute(cgemm_ca<1>,
                         cudaFuncAttributeMaxDynamicSharedMemorySize, CG_SMEM);
    cudaFuncSetAttribute(cgemm_ca<2>,
                         cudaFuncAttributeMaxDynamicSharedMemorySize, CG_SMEM);

    init_kernel<<<EW / 256, 256>>>(x_r, x_i);

    for (int l = 0; l < DEPTH; l++) {
        const float* qr  = qkvwr + (size_t)l * INNER * DIMD;
        const float* qi  = qkvwi + (size_t)l * INNER * DIMD;
        const float* owr = outwr + (size_t)l * DIMD * INNER;
        const float* owi = outwi + (size_t)l * DIMD * INNER;
        const float* fwr = ffwr + (size_t)l * DIMD * DIMD;
        const float* fwi = ffwi + (size_t)l * DIMD * DIMD;

        // split this layer's 3 weight matrices into bf16 hi/lo planes
        split3_kernel<<<768, 256>>>(qr, qi, owr, owi, fwr, fwi);

        // z1 planes = CLN(x)
        cln_kernel<<<ROWS, 256>>>(xr, xi,
                                  ln1gr + l * DIMD, ln1br + l * DIMD,
                                  ln1gi + l * DIMD, ln1bi + l * DIMD, zp);
        // w = z1 @ Wqkv^T   -> d_out fp32 scratch
        cgemm_ca<0><<<gemm_grid, 256, CG_SMEM>>>(zp, ws,
                                                 wr, wi, INNER, DIMD,
                                                 nullptr, nullptr, nullptr, nullptr, 0);
        // ao planes = attention(w)
        flash_mma_kernel<<<dim3(NSEQ / 64, BB * HEADS), 128, FLASH_SMEM>>>(wr, wi, zp);
        // x += ao @ Wout^T + bias
        cgemm_ca<1><<<gemm_grid, 256, CG_SMEM>>>(zp, ws + (size_t)4 * WELEM,
                                                 xr, xi, DIMD, INNER,
                                                 outbr + l * DIMD, outbi + l * DIMD,
                                                 nullptr, nullptr, 0);
        // z2 planes = CLN(x)
        cln_kernel<<<ROWS, 256>>>(xr, xi,
                                  ln2gr + l * DIMD, ln2br + l * DIMD,
                                  ln2gi + l * DIMD, ln2bi + l * DIMD, zp);
        // x = CReLU(z2 + ps*(z2 @ Wff^T) - ps*pl)
        cgemm_ca<2><<<gemm_grid, 256, CG_SMEM>>>(zp, ws + (size_t)8 * WELEM,
                                                 xr, xi, DIMD, DIMD,
                                                 nullptr, nullptr, stepv, lambv, l);
    }

    output_kernel<<<EW / 256, 256>>>((float*)d_out);
}

// round 17
// speedup vs baseline: 1.0383x; 1.0383x over previous
#include <cuda_runtime.h>
#include <math.h>
#include <stdint.h>

// Problem constants
#define BB     8
#define NSEQ   512
#define DIMD   512
#define DEPTH  6
#define HEADS  8
#define DH     64
#define INNER  512          // HEADS*DH
#define ROWS   4096         // BB*NSEQ
#define EPSL   1e-5f
#define ASCALE 0.125f       // DH^-0.5

// ---------------------------------------------------------------------------
// Scratch: 32 MB of __device__ globals. w/qkv buffer lives in d_out.
// ---------------------------------------------------------------------------
__device__ float g_x_r[ROWS * DIMD];
__device__ float g_x_i[ROWS * DIMD];
__device__ float g_z_r[ROWS * DIMD];
__device__ float g_z_i[ROWS * DIMD];

// ---------------------------------------------------------------------------
// Common mma/split helpers (verified R5-R11)
// ---------------------------------------------------------------------------
__device__ __forceinline__ void mma16(float* c, const uint32_t* a, const uint32_t* b) {
    asm volatile(
        "mma.sync.aligned.m16n8k16.row.col.f32.bf16.bf16.f32 "
        "{%0,%1,%2,%3}, {%4,%5,%6,%7}, {%8,%9}, {%0,%1,%2,%3};\n"
        : "+f"(c[0]), "+f"(c[1]), "+f"(c[2]), "+f"(c[3])
        : "r"(a[0]), "r"(a[1]), "r"(a[2]), "r"(a[3]), "r"(b[0]), "r"(b[1]));
}
__device__ __forceinline__ uint32_t pkbf(float lo_val, float hi_val) {
    uint32_t r;
    asm("cvt.rn.bf16x2.f32 %0, %1, %2;" : "=r"(r) : "f"(hi_val), "f"(lo_val));
    return r;
}
__device__ __forceinline__ uint32_t hi2(float a, float b) {
    uint32_t r;
    asm("prmt.b32 %0, %1, %2, 0x7632;" : "=r"(r)
        : "r"(__float_as_uint(a)), "r"(__float_as_uint(b)));
    return r;
}
__device__ __forceinline__ float lof(float a) {
    return a - __uint_as_float(__float_as_uint(a) & 0xffff0000u);
}
__device__ __forceinline__ void st_split(uint16_t* hiP, uint16_t* loP, int e, float4 v) {
    *(uint2*)&hiP[e] = make_uint2(hi2(v.x, v.y), hi2(v.z, v.w));
    *(uint2*)&loP[e] = make_uint2(pkbf(lof(v.x), lof(v.y)), pkbf(lof(v.z), lof(v.w)));
}
__device__ __forceinline__ void ldsm4(uint32_t* d, const uint16_t* p) {
    uint32_t a = (uint32_t)__cvta_generic_to_shared(p);
    asm volatile("ldmatrix.sync.aligned.m8n8.x4.shared.b16 {%0,%1,%2,%3}, [%4];"
        : "=r"(d[0]), "=r"(d[1]), "=r"(d[2]), "=r"(d[3]) : "r"(a));
}
__device__ __forceinline__ void ldsm4t(uint32_t* d, const uint16_t* p) {
    uint32_t a = (uint32_t)__cvta_generic_to_shared(p);
    asm volatile("ldmatrix.sync.aligned.m8n8.x4.trans.shared.b16 {%0,%1,%2,%3}, [%4];"
        : "=r"(d[0]), "=r"(d[1]), "=r"(d[2]), "=r"(d[3]) : "r"(a));
}

// ---------------------------------------------------------------------------
// Block reduction helper (256 threads)
// ---------------------------------------------------------------------------
__device__ __forceinline__ float block_reduce(float v, float* sh, bool ismax) {
    #pragma unroll
    for (int o = 16; o; o >>= 1) {
        float u = __shfl_xor_sync(0xffffffffu, v, o);
        v = ismax ? fmaxf(v, u) : (v + u);
    }
    int w = threadIdx.x >> 5;
    if ((threadIdx.x & 31) == 0) sh[w] = v;
    __syncthreads();
    if (threadIdx.x < 32) {
        float u = (threadIdx.x < 8) ? sh[threadIdx.x] : (ismax ? -INFINITY : 0.0f);
        #pragma unroll
        for (int o = 4; o; o >>= 1) {
            float t2 = __shfl_xor_sync(0xffffffffu, u, o);
            u = ismax ? fmaxf(u, t2) : (u + t2);
        }
        if (threadIdx.x == 0) sh[0] = u;
    }
    __syncthreads();
    float r = sh[0];
    __syncthreads();
    return r;
}

// ---------------------------------------------------------------------------
// Complex LayerNorm. One block (256 threads) per row of 512.
// ---------------------------------------------------------------------------
__global__ __launch_bounds__(256) void cln_kernel(
    const float* __restrict__ xr, const float* __restrict__ xi,
    const float* __restrict__ gr, const float* __restrict__ br,
    const float* __restrict__ gi, const float* __restrict__ bi,
    float* __restrict__ zr, float* __restrict__ zi)
{
    __shared__ float sh[8];
    int row = blockIdx.x;
    int t = threadIdx.x;
    const float* pr = xr + (size_t)row * DIMD;
    const float* pi = xi + (size_t)row * DIMD;

    float r0 = pr[t], r1 = pr[t + 256];
    float i0 = pi[t], i1 = pi[t + 256];

    float sr  = block_reduce(r0 + r1, sh, false);
    float ssr = block_reduce(r0 * r0 + r1 * r1, sh, false);
    float si  = block_reduce(i0 + i1, sh, false);
    float ssi = block_reduce(i0 * i0 + i1 * i1, sh, false);

    float mr = sr * (1.0f / DIMD);
    float vr = fmaxf(ssr * (1.0f / DIMD) - mr * mr, 0.0f);
    float rsr = rsqrtf(vr + EPSL);
    float mi = si * (1.0f / DIMD);
    float vi = fmaxf(ssi * (1.0f / DIMD) - mi * mi, 0.0f);
    float rsi = rsqrtf(vi + EPSL);

    float* qr = zr + (size_t)row * DIMD;
    float* qi = zi + (size_t)row * DIMD;
    qr[t]       = (r0 - mr) * rsr * gr[t]       + br[t];
    qr[t + 256] = (r1 - mr) * rsr * gr[t + 256] + br[t + 256];
    qi[t]       = (i0 - mi) * rsi * gi[t]       + bi[t];
    qi[t + 256] = (i1 - mi) * rsi * gi[t + 256] + bi[t + 256];
}

// ---------------------------------------------------------------------------
// bf16x3 complex NT GEMM — R11 body with INTERLEAVED mma ordering:
// consecutive mmas never target the same accumulator (distance 4), breaking
// the HMMA RAW chain. Per-accumulator term order unchanged (bit-identical).
// CTA 128x128, BK=16, 256 threads, warp tile 32x64, double-buffered.
// Epilogues: 0 plain / 1 residual+bias / 2 ISTA+CReLU.
// ---------------------------------------------------------------------------
#define PADK 24
#define APLN (128 * PADK)
#define STG  (8 * APLN)
#define CG_SMEM (2 * STG * 2)

#define LD32(P, r, k) (*(const uint32_t*)&(P)[(r) * PADK + (k)])

template <int EPI>
__global__ __launch_bounds__(256) void cgemm_bf16x3(
    const float* __restrict__ Ar, const float* __restrict__ Ai, int lda,
    const float* __restrict__ Br, const float* __restrict__ Bi, int ldb,
    float* __restrict__ Cr, float* __restrict__ Ci, int ldc, int K,
    const float* __restrict__ biasr, const float* __restrict__ biasi,
    const float* __restrict__ stepp, const float* __restrict__ lamp, int l)
{
    extern __shared__ uint16_t smem16[];

    int tid = threadIdx.x;
    int lane = tid & 31, w = tid >> 5;
    int wm = (w & 3) * 32, wn = (w >> 2) * 64;
    int gid = lane >> 2, tig = lane & 3;
    int row0 = blockIdx.y * 128, col0 = blockIdx.x * 128;

    float cr[2][8][4] = {}, ci[2][8][4] = {};
    float4 pa_r[2], pa_i[2], pb_r[2], pb_i[2];

    #define FETCH(k0)                                                          \
        {                                                                      \
            _Pragma("unroll")                                                  \
            for (int i = 0; i < 2; i++) {                                      \
                int idx = tid + i * 256;                                       \
                int m = idx >> 2, kq = idx & 3;                                \
                pa_r[i] = *(const float4*)&Ar[(size_t)(row0 + m) * lda + (k0) + kq * 4]; \
                pa_i[i] = *(const float4*)&Ai[(size_t)(row0 + m) * lda + (k0) + kq * 4]; \
                pb_r[i] = *(const float4*)&Br[(size_t)(col0 + m) * ldb + (k0) + kq * 4]; \
                pb_i[i] = *(const float4*)&Bi[(size_t)(col0 + m) * ldb + (k0) + kq * 4]; \
            }                                                                  \
        }

    #define STORE_SM(base)                                                     \
        {                                                                      \
            _Pragma("unroll")                                                  \
            for (int i = 0; i < 2; i++) {                                      \
                int idx = tid + i * 256;                                       \
                int m = idx >> 2, kq = idx & 3;                                \
                int e = m * PADK + kq * 4;                                     \
                st_split((base),            (base) + APLN,     e, pa_r[i]);    \
                st_split((base) + 2 * APLN, (base) + 3 * APLN, e, pa_i[i]);    \
                st_split((base) + 4 * APLN, (base) + 5 * APLN, e, pb_r[i]);    \
                st_split((base) + 6 * APLN, (base) + 7 * APLN, e, pb_i[i]);    \
            }                                                                  \
        }

    FETCH(0);
    STORE_SM(smem16);
    __syncthreads();

    int nstage = K >> 4;
    for (int s = 0; s < nstage; s++) {
        uint16_t* cur = smem16 + (s & 1) * STG;
        uint16_t* nxt = smem16 + ((s + 1) & 1) * STG;
        if (s + 1 < nstage) FETCH((s + 1) * 16);

        const uint16_t* ARH = cur;
        const uint16_t* ARL = cur + APLN;
        const uint16_t* AIH = cur + 2 * APLN;
        const uint16_t* AIL = cur + 3 * APLN;
        const uint16_t* BRH = cur + 4 * APLN;
        const uint16_t* BRL = cur + 5 * APLN;
        const uint16_t* BIH = cur + 6 * APLN;
        const uint16_t* BIL = cur + 7 * APLN;

        int kk = tig * 2;
        uint32_t aRH[2][4], aRL[2][4], aIH[2][4], aIL[2][4];
        #pragma unroll
        for (int mt = 0; mt < 2; mt++) {
            int r = wm + mt * 16 + gid;
            aRH[mt][0] = LD32(ARH, r, kk);     aRH[mt][1] = LD32(ARH, r + 8, kk);
            aRH[mt][2] = LD32(ARH, r, kk + 8); aRH[mt][3] = LD32(ARH, r + 8, kk + 8);
            aRL[mt][0] = LD32(ARL, r, kk);     aRL[mt][1] = LD32(ARL, r + 8, kk);
            aRL[mt][2] = LD32(ARL, r, kk + 8); aRL[mt][3] = LD32(ARL, r + 8, kk + 8);
            aIH[mt][0] = LD32(AIH, r, kk);     aIH[mt][1] = LD32(AIH, r + 8, kk);
            aIH[mt][2] = LD32(AIH, r, kk + 8); aIH[mt][3] = LD32(AIH, r + 8, kk + 8);
            aIL[mt][0] = LD32(AIL, r, kk);     aIL[mt][1] = LD32(AIL, r + 8, kk);
            aIL[mt][2] = LD32(AIL, r, kk + 8); aIL[mt][3] = LD32(AIL, r + 8, kk + 8);
        }
        #pragma unroll
        for (int nt = 0; nt < 8; nt++) {
            int c = wn + nt * 8 + gid;
            uint32_t bRH[2] = { LD32(BRH, c, kk), LD32(BRH, c, kk + 8) };
            uint32_t bRL[2] = { LD32(BRL, c, kk), LD32(BRL, c, kk + 8) };
            uint32_t bIH[2] = { LD32(BIH, c, kk), LD32(BIH, c, kk + 8) };
            uint32_t bIL[2] = { LD32(BIL, c, kk), LD32(BIL, c, kk + 8) };
            uint32_t nIH[2] = { bIH[0] ^ 0x80008000u, bIH[1] ^ 0x80008000u };
            uint32_t nIL[2] = { bIL[0] ^ 0x80008000u, bIL[1] ^ 0x80008000u };
            // interleaved: each accumulator hit every 4th mma (RAW chain broken);
            // per-accumulator term order identical to R11 (bit-exact result)
            mma16(cr[0][nt], aRH[0], bRH); mma16(ci[0][nt], aRH[0], bIH);
            mma16(cr[1][nt], aRH[1], bRH); mma16(ci[1][nt], aRH[1], bIH);
            mma16(cr[0][nt], aRH[0], bRL); mma16(ci[0][nt], aRH[0], bIL);
            mma16(cr[1][nt], aRH[1], bRL); mma16(ci[1][nt], aRH[1], bIL);
            mma16(cr[0][nt], aRL[0], bRH); mma16(ci[0][nt], aRL[0], bIH);
            mma16(cr[1][nt], aRL[1], bRH); mma16(ci[1][nt], aRL[1], bIH);
            mma16(cr[0][nt], aIH[0], nIH); mma16(ci[0][nt], aIH[0], bRH);
            mma16(cr[1][nt], aIH[1], nIH); mma16(ci[1][nt], aIH[1], bRH);
            mma16(cr[0][nt], aIH[0], nIL); mma16(ci[0][nt], aIH[0], bRL);
            mma16(cr[1][nt], aIH[1], nIL); mma16(ci[1][nt], aIH[1], bRL);
            mma16(cr[0][nt], aIL[0], nIH); mma16(ci[0][nt], aIL[0], bRH);
            mma16(cr[1][nt], aIL[1], nIH); mma16(ci[1][nt], aIL[1], bRH);
        }

        if (s + 1 < nstage) STORE_SM(nxt);
        __syncthreads();
    }
    #undef FETCH
    #undef STORE_SM

    float ps = 0.0f, pl = 0.0f;
    if (EPI == 2) {
        ps = log1pf(expf(stepp[l]));
        pl = log1pf(expf(lamp[l]));
    }

    #pragma unroll
    for (int mt = 0; mt < 2; mt++)
        #pragma unroll
        for (int nt = 0; nt < 8; nt++) {
            int m0 = row0 + wm + mt * 16 + gid;
            int n0 = col0 + wn + nt * 8 + tig * 2;
            #pragma unroll
            for (int half = 0; half < 2; half++) {
                int m = m0 + half * 8;
                float vr0 = cr[mt][nt][half * 2 + 0];
                float vr1 = cr[mt][nt][half * 2 + 1];
                float vi0 = ci[mt][nt][half * 2 + 0];
                float vi1 = ci[mt][nt][half * 2 + 1];
                size_t idx = (size_t)m * ldc + n0;
                if (EPI == 0) {
                    Cr[idx]     = vr0;  Cr[idx + 1] = vr1;
                    Ci[idx]     = vi0;  Ci[idx + 1] = vi1;
                } else if (EPI == 1) {
                    Cr[idx]     += vr0 + biasr[n0];
                    Cr[idx + 1] += vr1 + biasr[n0 + 1];
                    Ci[idx]     += vi0 + biasi[n0];
                    Ci[idx + 1] += vi1 + biasi[n0 + 1];
                } else {
                    size_t za = (size_t)m * lda + n0;
                    Cr[idx]     = fmaxf(Ar[za]     + ps * vr0 - ps * pl, 0.0f);
                    Cr[idx + 1] = fmaxf(Ar[za + 1] + ps * vr1 - ps * pl, 0.0f);
                    Ci[idx]     = fmaxf(Ai[za]     + ps * vi0, 0.0f);
                    Ci[idx + 1] = fmaxf(Ai[za + 1] + ps * vi1, 0.0f);
                }
            }
        }
}

// ---------------------------------------------------------------------------
// Tensor-core flash attention (bf16x3) — R9/R11 body with interleaved mma
// ordering in dots and AV (RAW chain distance 4, bit-identical accumulation).
// 64 q-rows / 4 warps per CTA, 2 CTAs per SM, ldmatrix(+trans) operands.
// ---------------------------------------------------------------------------
#define FSTR 72
#define QPL (64 * FSTR)
#define KPL (64 * FSTR)
#define FLASH_SMEM ((4 * QPL + 4 * KPL) * 2)   // 73728 bytes

__global__ __launch_bounds__(128, 2) void flash_mma_kernel(
    const float* __restrict__ Wr, const float* __restrict__ Wi,
    float* __restrict__ Or, float* __restrict__ Oi)
{
    extern __shared__ uint16_t fsm[];
    uint16_t* QRH = fsm;
    uint16_t* QRL = QRH + QPL;
    uint16_t* QIH = QRL + QPL;
    uint16_t* QIL = QIH + QPL;
    uint16_t* KRH = QIL + QPL;
    uint16_t* KRL = KRH + KPL;
    uint16_t* KIH = KRL + KPL;
    uint16_t* KIL = KIH + KPL;

    int tid = threadIdx.x;
    int lane = tid & 31, w = tid >> 5;   // w in 0..3
    int q0 = blockIdx.x * 64;
    int bh = blockIdx.y;
    int b = bh >> 3, h = bh & 7;

    const float* baseR = Wr + (size_t)b * NSEQ * INNER + h * DH;
    const float* baseI = Wi + (size_t)b * NSEQ * INNER + h * DH;

    #pragma unroll
    for (int i = 0; i < 8; i++) {
        int linear = tid + i * 128;
        int row = linear >> 4, c4 = linear & 15;
        float4 v = *(const float4*)&baseR[(size_t)(q0 + row) * INNER + c4 * 4];
        st_split(QRH, QRL, row * FSTR + c4 * 4, v);
        v = *(const float4*)&baseI[(size_t)(q0 + row) * INNER + c4 * 4];
        st_split(QIH, QIL, row * FSTR + c4 * 4, v);
    }

    int a_off = (16 * w + (lane & 7) + ((lane >> 3) & 1) * 8) * FSTR
              + ((lane >> 4) & 1) * 8;
    int bd_off = ((lane & 7) + ((lane >> 4) & 1) * 8) * FSTR
               + ((lane >> 3) & 1) * 8;
    int bv_off = ((lane & 7) + ((lane >> 3) & 1) * 8) * FSTR
               + ((lane >> 4) & 1) * 8;

    float o_r[8][4] = {}, o_i[8][4] = {};
    float mrow[2] = { -1e30f, -1e30f };
    float lrow[2] = { 0.0f, 0.0f };

    for (int kt = 0; kt < 8; kt++) {
        __syncthreads();
        #pragma unroll
        for (int i = 0; i < 8; i++) {
            int linear = tid + i * 128;
            int key = linear >> 4, c4 = linear & 15;
            int e = key * FSTR + c4 * 4;
            float4 v = *(const float4*)&baseR[(size_t)(kt * 64 + key) * INNER + c4 * 4];
            st_split(KRH, KRL, e, v);
            v = *(const float4*)&baseI[(size_t)(kt * 64 + key) * INNER + c4 * 4];
            st_split(KIH, KIL, e, v);
        }
        __syncthreads();

        // ---- dots (interleaved accumulators) ----
        float dr[8][4] = {}, di[8][4] = {};
        #pragma unroll 1
        for (int ks = 0; ks < 4; ks++) {
            int ao = a_off + ks * 16;
            uint32_t aRH[4], aRL[4], aIH[4], aIL[4];
            ldsm4(aRH, QRH + ao); ldsm4(aRL, QRL + ao);
            ldsm4(aIH, QIH + ao); ldsm4(aIL, QIL + ao);
            #pragma unroll
            for (int nfp = 0; nfp < 4; nfp++) {
                int bo = bd_off + nfp * 16 * FSTR + ks * 16;
                uint32_t BRH[4], BRL[4], BIH[4], BIL[4];
                ldsm4(BRH, KRH + bo); ldsm4(BRL, KRL + bo);
                ldsm4(BIH, KIH + bo); ldsm4(BIL, KIL + bo);
                int f0 = 2 * nfp, f1 = 2 * nfp + 1;
                uint32_t b0RH[2] = { BRH[0], BRH[1] }, b1RH[2] = { BRH[2], BRH[3] };
                uint32_t b0RL[2] = { BRL[0], BRL[1] }, b1RL[2] = { BRL[2], BRL[3] };
                uint32_t b0IH[2] = { BIH[0], BIH[1] }, b1IH[2] = { BIH[2], BIH[3] };
                uint32_t b0IL[2] = { BIL[0], BIL[1] }, b1IL[2] = { BIL[2], BIL[3] };
                uint32_t n0IH[2] = { b0IH[0] ^ 0x80008000u, b0IH[1] ^ 0x80008000u };
                uint32_t n0IL[2] = { b0IL[0] ^ 0x80008000u, b0IL[1] ^ 0x80008000u };
                uint32_t n1IH[2] = { b1IH[0] ^ 0x80008000u, b1IH[1] ^ 0x80008000u };
                uint32_t n1IL[2] = { b1IL[0] ^ 0x80008000u, b1IL[1] ^ 0x80008000u };
                mma16(dr[f0], aRH, b0RH); mma16(di[f0], aIH, b0RH);
                mma16(dr[f1], aRH, b1RH); mma16(di[f1], aIH, b1RH);
                mma16(dr[f0], aRH, b0RL); mma16(di[f0], aIH, b0RL);
                mma16(dr[f1], aRH, b1RL); mma16(di[f1], aIH, b1RL);
                mma16(dr[f0], aRL, b0RH); mma16(di[f0], aIL, b0RH);
                mma16(dr[f1], aRL, b1RH); mma16(di[f1], aIL, b1RH);
                mma16(dr[f0], aIH, b0IH); mma16(di[f0], aRH, n0IH);
                mma16(dr[f1], aIH, b1IH); mma16(di[f1], aRH, n1IH);
                mma16(dr[f0], aIH, b0IL); mma16(di[f0], aRH, n0IL);
                mma16(dr[f1], aIH, b1IL); mma16(di[f1], aRH, n1IL);
                mma16(dr[f0], aIL, b0IH); mma16(di[f0], aRL, n0IH);
                mma16(dr[f1], aIL, b1IH); mma16(di[f1], aRL, n1IH);
            }
        }

        // ---- online softmax ----
        float m2max[2] = { -1.0f, -1.0f };
        #pragma unroll
        for (int nf = 0; nf < 8; nf++)
            #pragma unroll
            for (int e = 0; e < 4; e++) {
                float m2 = dr[nf][e] * dr[nf][e] + di[nf][e] * di[nf][e];
                m2max[e >> 1] = fmaxf(m2max[e >> 1], m2);
            }
        float mnew[2];
        #pragma unroll
        for (int half = 0; half < 2; half++) {
            float v = m2max[half];
            v = fmaxf(v, __shfl_xor_sync(0xffffffffu, v, 1));
            v = fmaxf(v, __shfl_xor_sync(0xffffffffu, v, 2));
            mnew[half] = fmaxf(mrow[half], ASCALE * sqrtf(fmaxf(v, 0.0f)));
        }
        float sc0 = __expf(mrow[0] - mnew[0]);
        float sc1 = __expf(mrow[1] - mnew[1]);
        lrow[0] *= sc0; lrow[1] *= sc1;
        mrow[0] = mnew[0]; mrow[1] = mnew[1];
        #pragma unroll
        for (int nf = 0; nf < 8; nf++) {
            o_r[nf][0] *= sc0; o_r[nf][1] *= sc0;
            o_r[nf][2] *= sc1; o_r[nf][3] *= sc1;
            o_i[nf][0] *= sc0; o_i[nf][1] *= sc0;
            o_i[nf][2] *= sc1; o_i[nf][3] *= sc1;
        }
        float rsum[2] = { 0.0f, 0.0f };
        #pragma unroll
        for (int nf = 0; nf < 8; nf++)
            #pragma unroll
            for (int e = 0; e < 4; e++) {
                float m2 = dr[nf][e] * dr[nf][e] + di[nf][e] * di[nf][e];
                if (m2 > 0.0f) {
                    float rs = rsqrtf(m2);
                    float s = m2 * rs;
                    float p = __expf(ASCALE * s - mrow[e >> 1]);
                    rsum[e >> 1] += p;
                    float f = p * rs;
                    dr[nf][e] *= f;
                    di[nf][e] *= f;
                } else {
                    float p = __expf(-mrow[e >> 1]);
                    rsum[e >> 1] += p;
                    dr[nf][e] = p;
                    di[nf][e] = 0.0f;
                }
            }
        #pragma unroll
        for (int half = 0; half < 2; half++) {
            float v = rsum[half];
            v += __shfl_xor_sync(0xffffffffu, v, 1);
            v += __shfl_xor_sync(0xffffffffu, v, 2);
            lrow[half] += v;
        }

        // ---- AV (interleaved accumulators) ----
        #pragma unroll
        for (int t = 0; t < 4; t++) {
            uint32_t PrH[4] = { hi2(dr[2*t][0], dr[2*t][1]),   hi2(dr[2*t][2], dr[2*t][3]),
                                hi2(dr[2*t+1][0], dr[2*t+1][1]), hi2(dr[2*t+1][2], dr[2*t+1][3]) };
            uint32_t PrL[4] = { pkbf(lof(dr[2*t][0]), lof(dr[2*t][1])),
                                pkbf(lof(dr[2*t][2]), lof(dr[2*t][3])),
                                pkbf(lof(dr[2*t+1][0]), lof(dr[2*t+1][1])),
                                pkbf(lof(dr[2*t+1][2]), lof(dr[2*t+1][3])) };
            uint32_t PiH[4] = { hi2(di[2*t][0], di[2*t][1]),   hi2(di[2*t][2], di[2*t][3]),
                                hi2(di[2*t+1][0], di[2*t+1][1]), hi2(di[2*t+1][2], di[2*t+1][3]) };
            uint32_t PiL[4] = { pkbf(lof(di[2*t][0]), lof(di[2*t][1])),
                                pkbf(lof(di[2*t][2]), lof(di[2*t][3])),
                                pkbf(lof(di[2*t+1][0]), lof(di[2*t+1][1])),
                                pkbf(lof(di[2*t+1][2]), lof(di[2*t+1][3])) };
            #pragma unroll
            for (int nfp = 0; nfp < 4; nfp++) {
                int bo = bv_off + t * 16 * FSTR + nfp * 16;
                uint32_t BRH[4], BRL[4], BIH[4], BIL[4];
                ldsm4t(BRH, KRH + bo); ldsm4t(BRL, KRL + bo);
                ldsm4t(BIH, KIH + bo); ldsm4t(BIL, KIL + bo);
                int f0 = 2 * nfp, f1 = 2 * nfp + 1;
                uint32_t b0RH[2] = { BRH[0], BRH[1] }, b1RH[2] = { BRH[2], BRH[3] };
                uint32_t b0RL[2] = { BRL[0], BRL[1] }, b1RL[2] = { BRL[2], BRL[3] };
                uint32_t b0IH[2] = { BIH[0], BIH[1] }, b1IH[2] = { BIH[2], BIH[3] };
                uint32_t b0IL[2] = { BIL[0], BIL[1] }, b1IL[2] = { BIL[2], BIL[3] };
                uint32_t n0IH[2] = { b0IH[0] ^ 0x80008000u, b0IH[1] ^ 0x80008000u };
                uint32_t n0IL[2] = { b0IL[0] ^ 0x80008000u, b0IL[1] ^ 0x80008000u };
                uint32_t n1IH[2] = { b1IH[0] ^ 0x80008000u, b1IH[1] ^ 0x80008000u };
                uint32_t n1IL[2] = { b1IL[0] ^ 0x80008000u, b1IL[1] ^ 0x80008000u };
                mma16(o_r[f0], PrH, b0RH); mma16(o_i[f0], PrH, b0IH);
                mma16(o_r[f1], PrH, b1RH); mma16(o_i[f1], PrH, b1IH);
                mma16(o_r[f0], PrH, b0RL); mma16(o_i[f0], PrH, b0IL);
                mma16(o_r[f1], PrH, b1RL); mma16(o_i[f1], PrH, b1IL);
                mma16(o_r[f0], PrL, b0RH); mma16(o_i[f0], PrL, b0IH);
                mma16(o_r[f1], PrL, b1RH); mma16(o_i[f1], PrL, b1IH);
                mma16(o_r[f0], PiH, n0IH); mma16(o_i[f0], PiH, b0RH);
                mma16(o_r[f1], PiH, n1IH); mma16(o_i[f1], PiH, b1RH);
                mma16(o_r[f0], PiH, n0IL); mma16(o_i[f0], PiH, b0RL);
                mma16(o_r[f1], PiH, n1IL); mma16(o_i[f1], PiH, b1RL);
                mma16(o_r[f0], PiL, n0IH); mma16(o_i[f0], PiL, b0RH);
                mma16(o_r[f1], PiL, n1IH); mma16(o_i[f1], PiL, b1RH);
            }
        }
    }

    // ---- normalize + write O ----
    int gid = lane >> 2, tig = lane & 3;
    float inv0 = 1.0f / lrow[0];
    float inv1 = 1.0f / lrow[1];
    size_t row0g = (size_t)(b * NSEQ + q0 + 16 * w + gid);
    #pragma unroll
    for (int nf = 0; nf < 8; nf++) {
        int col = h * DH + nf * 8 + tig * 2;
        *(float2*)&Or[row0g * INNER + col] =
            make_float2(o_r[nf][0] * inv0, o_r[nf][1] * inv0);
        *(float2*)&Or[(row0g + 8) * INNER + col] =
            make_float2(o_r[nf][2] * inv1, o_r[nf][3] * inv1);
        *(float2*)&Oi[row0g * INNER + col] =
            make_float2(o_i[nf][0] * inv0, o_i[nf][1] * inv0);
        *(float2*)&Oi[(row0g + 8) * INNER + col] =
            make_float2(o_i[nf][2] * inv1, o_i[nf][3] * inv1);
    }
}

__global__ __launch_bounds__(256) void init_kernel(
    const float* __restrict__ xr, const float* __restrict__ xi)
{
    int i = blockIdx.x * 256 + threadIdx.x;
    g_x_r[i] = xr[i];
    g_x_i[i] = xi[i];
}

__global__ __launch_bounds__(256) void output_kernel(float* __restrict__ out)
{
    int i = blockIdx.x * 256 + threadIdx.x;
    out[i] = g_x_r[i];
    out[i + ROWS * DIMD] = g_x_i[i];
}

// ---------------------------------------------------------------------------
// Launch
// ---------------------------------------------------------------------------
extern "C" void kernel_launch(void* const* d_in, const int* in_sizes, int n_in,
                              void* d_out, int out_size)
{
    const float* x_r   = (const float*)d_in[0];
    const float* x_i   = (const float*)d_in[1];
    const float* ln1gr = (const float*)d_in[2];
    const float* ln1gi = (const float*)d_in[3];
    const float* ln2gr = (const float*)d_in[4];
    const float* ln2gi = (const float*)d_in[5];
    const float* ln1br = (const float*)d_in[6];
    const float* ln1bi = (const float*)d_in[7];
    const float* ln2br = (const float*)d_in[8];
    const float* ln2bi = (const float*)d_in[9];
    const float* qkvwr = (const float*)d_in[10];
    const float* qkvwi = (const float*)d_in[11];
    const float* outwr = (const float*)d_in[12];
    const float* outwi = (const float*)d_in[13];
    const float* outbr = (const float*)d_in[14];
    const float* outbi = (const float*)d_in[15];
    const float* ffwr  = (const float*)d_in[16];
    const float* ffwi  = (const float*)d_in[17];
    const float* stepv = (const float*)d_in[18];
    const float* lambv = (const float*)d_in[19];

    const int EW = ROWS * DIMD;
    const dim3 gemm_grid(DIMD / 128, ROWS / 128);   // (4, 32) = 128 blocks

    float* wr = (float*)d_out;
    float* wi = wr + (size_t)ROWS * INNER;

    float *xr, *xi, *zr, *zi;
    cudaGetSymbolAddress((void**)&xr, g_x_r);
    cudaGetSymbolAddress((void**)&xi, g_x_i);
    cudaGetSymbolAddress((void**)&zr, g_z_r);
    cudaGetSymbolAddress((void**)&zi, g_z_i);

    cudaFuncSetAttribute(flash_mma_kernel,
                         cudaFuncAttributeMaxDynamicSharedMemorySize, FLASH_SMEM);
    cudaFuncSetAttribute(cgemm_bf16x3<0>,
                         cudaFuncAttributeMaxDynamicSharedMemorySize, CG_SMEM);
    cudaFuncSetAttribute(cgemm_bf16x3<1>,
                         cudaFuncAttributeMaxDynamicSharedMemorySize, CG_SMEM);
    cudaFuncSetAttribute(cgemm_bf16x3<2>,
                         cudaFuncAttributeMaxDynamicSharedMemorySize, CG_SMEM);

    init_kernel<<<EW / 256, 256>>>(x_r, x_i);

    for (int l = 0; l < DEPTH; l++) {
        const float* qr  = qkvwr + (size_t)l * INNER * DIMD;
        const float* qi  = qkvwi + (size_t)l * INNER * DIMD;
        const float* owr = outwr + (size_t)l * DIMD * INNER;
        const float* owi = outwi + (size_t)l * DIMD * INNER;
        const float* fwr = ffwr + (size_t)l * DIMD * DIMD;
        const float* fwi = ffwi + (size_t)l * DIMD * DIMD;

        // z1 = CLN(x)
        cln_kernel<<<ROWS, 256>>>(xr, xi,
                                  ln1gr + l * DIMD, ln1br + l * DIMD,
                                  ln1gi + l * DIMD, ln1bi + l * DIMD,
                                  zr, zi);
        // w = z1 @ Wqkv^T   -> d_out scratch
        cgemm_bf16x3<0><<<gemm_grid, 256, CG_SMEM>>>(zr, zi, DIMD, qr, qi, DIMD,
                                                     wr, wi, INNER, DIMD,
                                                     nullptr, nullptr, nullptr, nullptr, 0);
        // ao = attention(w) -> z buffer
        flash_mma_kernel<<<dim3(NSEQ / 64, BB * HEADS), 128, FLASH_SMEM>>>(wr, wi, zr, zi);
        // x += ao @ Wout^T + bias
        cgemm_bf16x3<1><<<gemm_grid, 256, CG_SMEM>>>(zr, zi, INNER, owr, owi, INNER,
                                                     xr, xi, DIMD, INNER,
                                                     outbr + l * DIMD, outbi + l * DIMD,
                                                     nullptr, nullptr, 0);
        // z2 = CLN(x)
        cln_kernel<<<ROWS, 256>>>(xr, xi,
                                  ln2gr + l * DIMD, ln2br + l * DIMD,
                                  ln2gi + l * DIMD, ln2bi + l * DIMD,
                                  zr, zi);
        // x = CReLU(z2 + ps*(z2 @ Wff^T) - ps*pl)
        cgemm_bf16x3<2><<<gemm_grid, 256, CG_SMEM>>>(zr, zi, DIMD, fwr, fwi, DIMD,
                                                     xr, xi, DIMD, DIMD,
                                                     nullptr, nullptr, stepv, lambv, l);
    }

    output_kernel<<<EW / 256, 256>>>((float*)d_out);
}